// round 16
// baseline (speedup 1.0000x reference)
#include <cuda_runtime.h>
#include <cstdint>

#define BB 64
#define SS 512
#define HH 1024
#define LL 9
#define NC 32          // chunks per batch
#define CHUNK 16       // steps per chunk == rows per block
#define RPW 2          // rows per warp (8 warps x 2 = 16)
#define RPB 16

// scratch (static __device__, zero-initialized — no allocations)
__device__ float g_logits[BB*SS*LL];     // [B,S,L] fc outputs (finale gold score)
__device__ float g_chunks[BB*NC*81];     // per-(batch,chunk) 9x9 transfer matrices
__device__ float g_pb[BB];               // per-batch (norm - score)
__device__ int   g_cnt[BB];              // per-batch completion counters (self-reset)
__device__ int   g_ticket;               // global ticket (self-reset)

// monotone int key for fp32 max (order-preserving bijection)
__device__ __forceinline__ int f2key(float x) {
    int b = __float_as_int(x);
    return b ^ ((b >> 31) | 0x80000000);
}
__device__ __forceinline__ float key2f(int k) {
    return __int_as_float(k ^ ((k >= 0) ? 0xFFFFFFFF : 0x80000000));
}

// ---------------------------------------------------------------------------
// Single fused kernel. Block (b,c) with blk = b*32 + c:
//  P1: GEMV logits for rows b*512 + [16c, 16c+16)  (8 warps x 2 rows, W in SMEM,
//      register double-buffered LDG.128) -> emit_sh + g_logits
//  P2: warps 0-2 fold chunk c's steps (t in [16c,16c+16) ∩ [1,512)) into a 9x9
//      log-semiring transfer matrix, probability-domain (1 exp + 1 log / step)
//  P3: last block per batch: gold score (256 thr) + alpha compose (warp 0,
//      matrices prefetched into SMEM aliasing Wsh); last batch writes mean.
// Labels are int32 (JAX x64 disabled makes .astype(int64) a no-op).
// ---------------------------------------------------------------------------
__global__ __launch_bounds__(256, 4) void k_fused(const float* __restrict__ X,
                                                  const float* __restrict__ W,
                                                  const float* __restrict__ bias,
                                                  const float* __restrict__ trans,
                                                  const int* __restrict__ mask,
                                                  const int* __restrict__ labels,
                                                  const float* __restrict__ startv,
                                                  const float* __restrict__ endv,
                                                  float* __restrict__ out) {
    __shared__ float4 Wsh[LL*(HH/4)];      // 36 KB; aliased as chunks_sh in P3
    __shared__ float  emit_sh[CHUNK][LL];
    __shared__ int    mask_sh[CHUNK];
    __shared__ float  redf[256];
    __shared__ int    redi[256];
    __shared__ int    is_last_sh;

    const int tid  = threadIdx.x;
    const int warp = tid >> 5;
    const int lane = tid & 31;
    const int blk  = blockIdx.x;
    const int b    = blk >> 5;            // batch
    const int c    = blk & 31;            // chunk

    // ---------------- phase 1: GEMV ----------------
    const float4* W4 = reinterpret_cast<const float4*>(W);
    for (int idx = tid; idx < LL*(HH/4); idx += 256) Wsh[idx] = W4[idx];
    if (tid < CHUNK) mask_sh[tid] = mask[b*SS + c*CHUNK + tid];
    __syncthreads();

    const int row0 = blk * RPB + warp * RPW;
    const float4* Xr0 = reinterpret_cast<const float4*>(X) + (size_t)row0 * (HH/4);
    const float4* Xr1 = Xr0 + (HH/4);

    float acc[RPW][LL];
    #pragma unroll
    for (int r = 0; r < RPW; r++)
        #pragma unroll
        for (int j = 0; j < LL; j++) acc[r][j] = 0.f;

    float4 cur4[2][RPW], nxt4[2][RPW];
    cur4[0][0] = Xr0[lane];        cur4[0][1] = Xr1[lane];
    cur4[1][0] = Xr0[32 + lane];   cur4[1][1] = Xr1[32 + lane];

    #pragma unroll
    for (int g = 0; g < 4; g++) {
        if (g < 3) {               // prefetch k-iters 2g+2, 2g+3
            const int c0 = (2*g + 2)*32 + lane;
            nxt4[0][0] = Xr0[c0];      nxt4[0][1] = Xr1[c0];
            nxt4[1][0] = Xr0[c0 + 32]; nxt4[1][1] = Xr1[c0 + 32];
        }
        #pragma unroll
        for (int u = 0; u < 2; u++) {
            const int col = (2*g + u)*32 + lane;
            #pragma unroll
            for (int j = 0; j < LL; j++) {
                const float4 w = Wsh[j*(HH/4) + col];
                #pragma unroll
                for (int r = 0; r < RPW; r++) {
                    acc[r][j] += cur4[u][r].x*w.x;
                    acc[r][j] += cur4[u][r].y*w.y;
                    acc[r][j] += cur4[u][r].z*w.z;
                    acc[r][j] += cur4[u][r].w*w.w;
                }
            }
        }
        #pragma unroll
        for (int u = 0; u < 2; u++)
            #pragma unroll
            for (int r = 0; r < RPW; r++) cur4[u][r] = nxt4[u][r];
    }

    #pragma unroll
    for (int r = 0; r < RPW; r++)
        #pragma unroll
        for (int j = 0; j < LL; j++) {
            float v = acc[r][j];
            v += __shfl_xor_sync(0xffffffffu, v, 16);
            v += __shfl_xor_sync(0xffffffffu, v, 8);
            v += __shfl_xor_sync(0xffffffffu, v, 4);
            v += __shfl_xor_sync(0xffffffffu, v, 2);
            v += __shfl_xor_sync(0xffffffffu, v, 1);
            acc[r][j] = v;
        }

    if (lane < LL) {
        const float bj = __ldg(&bias[lane]);
        #pragma unroll
        for (int r = 0; r < RPW; r++) {
            const float val = acc[r][lane] + bj;
            g_logits[(size_t)(row0 + r)*LL + lane] = val;   // finale needs these
            emit_sh[warp*RPW + r][lane] = val;              // scan reads from smem
        }
    }
    __syncthreads();        // emit ready; Wsh dead from here on

    // ---------------- phase 2: chunk scan (warps 0..2) ----------------
    if (warp < 3) {
        const bool act   = lane < 27;
        const int  grp   = lane / LL;             // 0..3 (3 = tail)
        const int  base  = grp * LL;
        const int  i     = warp * 3 + grp;        // row (valid when act)
        const int  j     = lane % LL;             // column
        const unsigned gmask = (grp < 3) ? (0x1FFu << (grp * LL)) : 0xF8000000u;

        float tcol[LL], Ecol[LL];                 // trans[k][j], exp(trans[k][j])
        #pragma unroll
        for (int k = 0; k < LL; k++) {
            tcol[k] = trans[k*LL + j];
            Ecol[k] = __expf(tcol[k]);
        }

        const int s0 = (c == 0) ? 1 : 0;          // chunk 0 skips t=0 (alpha0)
        float curv = 0.f;
        if (act)
            curv = (mask_sh[s0] > 0) ? (tcol[i] + emit_sh[s0][j])
                                     : ((i == j) ? 0.f : -1e30f);

        for (int s = s0 + 1; s < CHUNK; s++) {
            const int   kmax = __reduce_max_sync(gmask, f2key(curv));
            const float mx   = key2f(kmax);
            const float e    = __expf(curv - mx);
            float p[LL];
            #pragma unroll
            for (int k = 0; k < LL; k++)
                p[k] = __shfl_sync(0xffffffffu, e, base + k) * Ecol[k];
            const float s01 = p[0]+p[1], s23 = p[2]+p[3];
            const float s45 = p[4]+p[5], s67 = p[6]+p[7];
            const float ssum = ((s01+s23)+(s45+s67)) + p[8];
            const float newv = emit_sh[s][j] + mx + __logf(ssum);
            curv = (mask_sh[s] > 0) ? newv : curv;
        }

        if (act) g_chunks[(size_t)(b*NC + c)*81 + i*LL + j] = curv;
    }

    // ---------------- per-batch ticket ----------------
    __threadfence();
    __syncthreads();
    if (tid == 0) {
        const int v = atomicAdd(&g_cnt[b], 1);
        is_last_sh = (v == NC - 1);
        if (v == NC - 1) g_cnt[b] = 0;            // self-reset for next replay
    }
    __syncthreads();
    if (!is_last_sh) return;
    __threadfence();   // order other blocks' g_chunks/g_logits stores before reads

    // ---------------- phase 3: finale ----------------
    float* chunks_sh = reinterpret_cast<float*>(Wsh);   // alias dead W storage
    for (int idx = tid; idx < NC*81; idx += 256)
        chunks_sh[idx] = g_chunks[(size_t)b*(NC*81) + idx];

    // gold path score with 256 threads
    float part = 0.f; int cnt = 0;
    for (int t = tid; t < SS; t += 256) {
        const int tag = labels[(size_t)b*SS + t];
        const int mi  = mask[b*SS + t];
        const float m = (mi > 0) ? 1.f : 0.f;
        cnt += (mi > 0);
        part += m * g_logits[((size_t)b*SS + t)*LL + tag];
        if (t >= 1) {
            const int tagp = labels[(size_t)b*SS + t - 1];
            part += m * trans[tagp*LL + tag];
        }
    }
    redf[tid] = part; redi[tid] = cnt;
    __syncthreads();                               // also publishes chunks_sh
    for (int s2 = 128; s2 > 0; s2 >>= 1) {
        if (tid < s2) { redf[tid] += redf[tid + s2]; redi[tid] += redi[tid + s2]; }
        __syncthreads();
    }

    if (warp == 0) {
        const int jj = (lane < LL) ? lane : 0;     // clamp for in-bounds reads

        // alpha0 = feats[0] + start (mask not applied at t=0, per reference)
        float a = g_logits[(size_t)b*SS*LL + jj] + startv[jj];

        for (int cc = 0; cc < NC; cc++) {
            const float* P = &chunks_sh[cc*81];
            float v[LL];
            float mx = -1e30f;
            #pragma unroll
            for (int k = 0; k < LL; k++) {
                v[k] = __shfl_sync(0xffffffffu, a, k) + P[k*LL + jj];
                mx = fmaxf(mx, v[k]);
            }
            float s = 0.f;
            #pragma unroll
            for (int k = 0; k < LL; k++) s += __expf(v[k] - mx);
            a = mx + __logf(s);
        }

        float av[LL];
        #pragma unroll
        for (int k = 0; k < LL; k++) av[k] = __shfl_sync(0xffffffffu, a, k);

        if (lane == 0) {
            float mx = -1e30f;
            #pragma unroll
            for (int k = 0; k < LL; k++) mx = fmaxf(mx, av[k] + endv[k]);
            float s = 0.f;
            #pragma unroll
            for (int k = 0; k < LL; k++) s += __expf(av[k] + endv[k] - mx);
            const float norm = mx + __logf(s);

            int last_idx = redi[0] - 1; if (last_idx < 0) last_idx = 0;
            const int tag0 = labels[(size_t)b*SS];
            const int tagL = labels[(size_t)b*SS + last_idx];
            g_pb[b] = norm - (redf[0] + startv[tag0] + endv[tagL]);

            __threadfence();
            const int t2 = atomicAdd(&g_ticket, 1);
            if (t2 == BB - 1) {                    // globally last batch
                __threadfence();
                float sum = 0.f;
                #pragma unroll
                for (int ib = 0; ib < BB; ib++) sum += g_pb[ib];
                out[0] = sum * (1.f / BB);
                g_ticket = 0;                      // self-reset for next replay
            }
        }
    }
}

extern "C" void kernel_launch(void* const* d_in, const int* in_sizes, int n_in,
                              void* d_out, int out_size) {
    const float* X      = (const float*)d_in[0];
    const int*   labels = (const int*)  d_in[1];   // int32 on device (JAX x64 off)
    const int*   mask   = (const int*)  d_in[2];
    const float* W      = (const float*)d_in[3];
    const float* bias   = (const float*)d_in[4];
    const float* trans  = (const float*)d_in[5];
    const float* startv = (const float*)d_in[6];
    const float* endv   = (const float*)d_in[7];

    k_fused<<<BB*NC, 256>>>(X, W, bias, trans, mask, labels, startv, endv,
                            (float*)d_out);
}